// round 5
// baseline (speedup 1.0000x reference)
#include <cuda_runtime.h>
#include <cuda_bf16.h>
#include <math.h>

#define N_NODES 200000
#define N_EDGES 6400000
#define F_IN    128
#define H1      16
#define C2      2

// ---------------- device scratch (no allocations allowed) ----------------
__device__ int   g_deg[N_NODES];      // in-degree
__device__ int   g_start[N_NODES];    // CSR segment start (arbitrary order)
__device__ int   g_cursor[N_NODES];   // placement cursors
__device__ float g_dinv[N_NODES];     // 1/sqrt(deg+1)
__device__ int   g_csr[N_EDGES];      // src ids grouped by dst
__device__ float g_h1s[N_NODES * H1]; // dinv * (x @ W1)
__device__ float g_h2s[N_NODES * C2]; // dinv * h2
__device__ int   g_total;             // segment allocator
__device__ int   g_is64;

// ---------------- zero degree counters + allocator ----------------
__global__ void k_zero() {
    int i = blockIdx.x * blockDim.x + threadIdx.x;
    if (i < N_NODES) g_deg[i] = 0;
    if (i == 0) g_total = 0;
}

// ---------------- detect int64 vs int32 edge_index ----------------
__global__ void k_detect(const void* __restrict__ ei) {
    __shared__ int bad;
    if (threadIdx.x == 0) bad = 0;
    __syncthreads();
    const long long* p = (const long long*)ei;
    for (int i = threadIdx.x; i < 1024; i += blockDim.x) {
        long long v = __ldg(p + i);
        if (v < 0 || v >= (long long)N_NODES) bad = 1;
    }
    __syncthreads();
    if (threadIdx.x == 0) g_is64 = bad ? 0 : 1;
}

// ---------------- in-degree count ----------------
__global__ void k_deg(const void* __restrict__ ei, int E) {
    int i = blockIdx.x * blockDim.x + threadIdx.x;
    if (i >= E) return;
    int d;
    if (g_is64) d = (int)__ldg((const long long*)ei + E + i);
    else        d = __ldg((const int*)ei + E + i);
    atomicAdd(&g_deg[d], 1);
}

// ---------------- segment assignment (block-aggregated allocator) --------
__global__ void k_assign(int n) {
    int i = blockIdx.x * blockDim.x + threadIdx.x;
    int lane = threadIdx.x & 31;
    int warp = threadIdx.x >> 5;
    int deg = (i < n) ? g_deg[i] : 0;

    int v = deg;
#pragma unroll
    for (int off = 1; off < 32; off <<= 1) {
        int t = __shfl_up_sync(0xffffffff, v, off);
        if (lane >= off) v += t;
    }
    __shared__ int wsum[8];
    if (lane == 31) wsum[warp] = v;
    __syncthreads();
    if (warp == 0 && lane < 8) {
        int w = wsum[lane];
#pragma unroll
        for (int off = 1; off < 8; off <<= 1) {
            int t = __shfl_up_sync(0xff, w, off, 8);
            if (lane >= off) w += t;
        }
        wsum[lane] = w;
    }
    __syncthreads();
    int blockExcl = (warp ? wsum[warp - 1] : 0) + (v - deg);
    int blockTotal = wsum[7];
    __shared__ int base;
    if (threadIdx.x == 0) base = atomicAdd(&g_total, blockTotal);
    __syncthreads();
    if (i < n) {
        int s = base + blockExcl;
        g_start[i] = s;
        g_cursor[i] = s;
        g_dinv[i] = rsqrtf((float)deg + 1.0f);
    }
}

// ---------------- CSR placement ----------------
__global__ void k_place(const void* __restrict__ ei, int E) {
    int i = blockIdx.x * blockDim.x + threadIdx.x;
    if (i >= E) return;
    int s, d;
    if (g_is64) {
        const long long* p = (const long long*)ei;
        s = (int)__ldg(p + i);
        d = (int)__ldg(p + E + i);
    } else {
        const int* p = (const int*)ei;
        s = __ldg(p + i);
        d = __ldg(p + E + i);
    }
    int pos = atomicAdd(&g_cursor[d], 1);
    g_csr[pos] = s;
}

// ---------------- h1s = dinv * (x @ W1)  (warp per node) ----------------
__global__ void k_h1(const float* __restrict__ x, const float* __restrict__ W1,
                     int n) {
    __shared__ float W1t[H1 * F_IN];  // transposed: [j][k]
    for (int t = threadIdx.x; t < F_IN * H1; t += blockDim.x) {
        int k = t / H1, j = t % H1;
        W1t[j * F_IN + k] = W1[t];
    }
    __syncthreads();

    int warp = (blockIdx.x * blockDim.x + threadIdx.x) >> 5;
    int lane = threadIdx.x & 31;
    if (warp >= n) return;

    float4 xv = ((const float4*)x)[warp * (F_IN / 4) + lane];

    float acc[H1];
#pragma unroll
    for (int j = 0; j < H1; j++) {
        float4 w = ((const float4*)W1t)[j * (F_IN / 4) + lane];
        acc[j] = xv.x * w.x + xv.y * w.y + xv.z * w.z + xv.w * w.w;
    }
#pragma unroll
    for (int off = 16; off; off >>= 1) {
#pragma unroll
        for (int j = 0; j < H1; j++)
            acc[j] += __shfl_xor_sync(0xffffffff, acc[j], off);
    }
    if (lane == 0) {
        float dn = g_dinv[warp];
        float4* o = (float4*)(g_h1s + warp * H1);
        o[0] = make_float4(dn * acc[0], dn * acc[1], dn * acc[2], dn * acc[3]);
        o[1] = make_float4(dn * acc[4], dn * acc[5], dn * acc[6], dn * acc[7]);
        o[2] = make_float4(dn * acc[8], dn * acc[9], dn * acc[10], dn * acc[11]);
        o[3] = make_float4(dn * acc[12], dn * acc[13], dn * acc[14], dn * acc[15]);
    }
}

// ---------------- layer-1 gather: 8 edges/iter, float4 per lane ----------
// lane>>2 = edge slot (8 edges in flight), lane&3 = float4 feature chunk.
// Per warp iteration: 1 coalesced 32B csr read + 8 independent 16B gathers.
__global__ void k_gather1(const float* __restrict__ b1,
                          const float* __restrict__ W2, int n) {
    __shared__ float sW2[H1 * C2];
    __shared__ float sb1[H1];
    if (threadIdx.x < H1 * C2) sW2[threadIdx.x] = W2[threadIdx.x];
    if (threadIdx.x < H1) sb1[threadIdx.x] = b1[threadIdx.x];
    __syncthreads();

    int node = (blockIdx.x * blockDim.x + threadIdx.x) >> 5;
    int lane = threadIdx.x & 31;
    if (node >= n) return;

    int start = g_start[node];
    int deg = g_deg[node];
    int eslot = lane >> 2;
    int chunk = lane & 3;
    const float4* __restrict__ h4 = (const float4*)g_h1s;

    float4 acc = make_float4(0.f, 0.f, 0.f, 0.f);
    int e = 0;
    // 2x unrolled: 16 edges per trip, 16 LDG.128 in flight per warp
    for (; e + 16 <= deg; e += 16) {
        int srcA = __ldg(&g_csr[start + e + eslot]);
        int srcB = __ldg(&g_csr[start + e + 8 + eslot]);
        float4 a = __ldg(&h4[srcA * 4 + chunk]);
        float4 b = __ldg(&h4[srcB * 4 + chunk]);
        acc.x += a.x + b.x;
        acc.y += a.y + b.y;
        acc.z += a.z + b.z;
        acc.w += a.w + b.w;
    }
    for (; e + 8 <= deg; e += 8) {
        int src = __ldg(&g_csr[start + e + eslot]);
        float4 a = __ldg(&h4[src * 4 + chunk]);
        acc.x += a.x; acc.y += a.y; acc.z += a.z; acc.w += a.w;
    }
    if (e + eslot < deg) {
        int src = __ldg(&g_csr[start + e + eslot]);
        float4 a = __ldg(&h4[src * 4 + chunk]);
        acc.x += a.x; acc.y += a.y; acc.z += a.z; acc.w += a.w;
    }

    // reduce over edge-slot bits (lane bits 2,3,4)
#pragma unroll
    for (int off = 4; off <= 16; off <<= 1) {
        acc.x += __shfl_xor_sync(0xffffffff, acc.x, off);
        acc.y += __shfl_xor_sync(0xffffffff, acc.y, off);
        acc.z += __shfl_xor_sync(0xffffffff, acc.z, off);
        acc.w += __shfl_xor_sync(0xffffffff, acc.w, off);
    }

    // epilogue: every lane handles its 4-feature chunk (replicated over eslot)
    float dn = g_dinv[node];
    float4 self = __ldg(&h4[node * 4 + chunk]);  // self-loop: dinv^2*h1 = dinv*h1s
    float z0 = fmaxf(dn * (acc.x + self.x) + sb1[chunk * 4 + 0], 0.f);
    float z1 = fmaxf(dn * (acc.y + self.y) + sb1[chunk * 4 + 1], 0.f);
    float z2 = fmaxf(dn * (acc.z + self.z) + sb1[chunk * 4 + 2], 0.f);
    float z3 = fmaxf(dn * (acc.w + self.w) + sb1[chunk * 4 + 3], 0.f);
    float o0 = z0 * sW2[(chunk * 4 + 0) * 2] + z1 * sW2[(chunk * 4 + 1) * 2] +
               z2 * sW2[(chunk * 4 + 2) * 2] + z3 * sW2[(chunk * 4 + 3) * 2];
    float o1 = z0 * sW2[(chunk * 4 + 0) * 2 + 1] + z1 * sW2[(chunk * 4 + 1) * 2 + 1] +
               z2 * sW2[(chunk * 4 + 2) * 2 + 1] + z3 * sW2[(chunk * 4 + 3) * 2 + 1];

    // reduce over chunk bits (lane bits 0,1)
#pragma unroll
    for (int off = 1; off <= 2; off <<= 1) {
        o0 += __shfl_xor_sync(0xffffffff, o0, off);
        o1 += __shfl_xor_sync(0xffffffff, o1, off);
    }
    if (lane == 0) {
        float2* o = (float2*)(g_h2s + node * C2);
        *o = make_float2(dn * o0, dn * o1);  // pre-scale for layer 2
    }
}

// ---------------- layer-2 gather + bias + log_softmax ----------------
__global__ void k_gather2(const float* __restrict__ b2, float* __restrict__ out,
                          int n) {
    int node = (blockIdx.x * blockDim.x + threadIdx.x) >> 5;
    int lane = threadIdx.x & 31;
    if (node >= n) return;

    int start = g_start[node];
    int deg = g_deg[node];

    float ax = 0.f, ay = 0.f;
    for (int e = lane; e < deg; e += 32) {
        int src = __ldg(&g_csr[start + e]);
        float2 v = *(const float2*)(g_h2s + src * C2);
        ax += v.x;
        ay += v.y;
    }
#pragma unroll
    for (int off = 16; off; off >>= 1) {
        ax += __shfl_xor_sync(0xffffffff, ax, off);
        ay += __shfl_xor_sync(0xffffffff, ay, off);
    }
    if (lane == 0) {
        float dn = g_dinv[node];
        float2 hs = *(const float2*)(g_h2s + node * C2);
        float o0 = dn * (ax + hs.x) + b2[0];
        float o1 = dn * (ay + hs.y) + b2[1];
        float m = fmaxf(o0, o1);
        float lse = m + logf(expf(o0 - m) + expf(o1 - m));
        float2* o = (float2*)(out + node * C2);
        *o = make_float2(o0 - lse, o1 - lse);
    }
}

extern "C" void kernel_launch(void* const* d_in, const int* in_sizes, int n_in,
                              void* d_out, int out_size) {
    const float* x = (const float*)d_in[0];
    const void* ei = d_in[1];
    const float* W1 = (const float*)d_in[2];
    const float* b1 = (const float*)d_in[3];
    const float* W2 = (const float*)d_in[4];
    const float* b2 = (const float*)d_in[5];
    float* out = (float*)d_out;

    const int n = in_sizes[0] / F_IN;   // 200000
    const int E = in_sizes[1] / 2;      // 6400000

    const int TB = 256;
    const int eBlocks = (E + TB - 1) / TB;
    const int nBlocks = (n + TB - 1) / TB;
    const int wBlocks = (n + (TB / 32) - 1) / (TB / 32);

    k_zero<<<nBlocks, TB>>>();
    k_detect<<<1, 256>>>(ei);
    k_deg<<<eBlocks, TB>>>(ei, E);
    k_assign<<<nBlocks, TB>>>(n);
    k_h1<<<wBlocks, TB>>>(x, W1, n);
    k_place<<<eBlocks, TB>>>(ei, E);
    k_gather1<<<wBlocks, TB>>>(b1, W2, n);
    k_gather2<<<wBlocks, TB>>>(b2, out, n);
}